// round 9
// baseline (speedup 1.0000x reference)
#include <cuda_runtime.h>
#include <cuda_bf16.h>
#include <cstddef>
#include <cstdint>

// Problem constants (B=4096, n=512, m=1024)
#define Bsz 4096
#define Nn  512
#define Mm  1024
#define STEPC 0.01f
#define TOLV 1e-5f

// ---- tensor tile config (cg1 peripheral GEMMs) ----
#define TM 128
#define TN 256
#define KC 64
#define TILEA_B 16384          // 128x64 bf16 tile bytes
#define TILEB_B 32768          // 256x64 bf16 tile bytes
#define OFF_ALO 16384
#define OFF_BHI 32768
#define OFF_BLO 65536
#define STG_SZ  98304          // 96 KB per stage
#define DSMEM   (2 * STG_SZ + 1024)

// ---- cg2 PGD config: per-CTA stage = A(16K hi+16K lo) + Bhalf(16K hi+16K lo)
#define STG2_SZ 65536
#define DSMEM2  (2 * STG2_SZ + 1024)

#if defined(__CUDA_ARCH__) && defined(__CUDA_ARCH_FEAT_SM103_ALL)
#define HAS_TCGEN05 1
#else
#define HAS_TCGEN05 0
#endif

// ---------------- device scratch (allocation-free) ----------------
__device__ __align__(128) float g_c[(size_t)Bsz * Mm];
__device__ __align__(128) float g_msk[(size_t)Bsz * Mm];
__device__ __align__(128) float g_act[(size_t)Bsz * Mm];
__device__ __align__(128) __nv_bfloat16 g_AAi_h[Mm * Nn];
__device__ __align__(128) __nv_bfloat16 g_AAi_l[Mm * Nn];
__device__ __align__(128) __nv_bfloat16 g_ABi_h[Mm * Nn];
__device__ __align__(128) __nv_bfloat16 g_ABi_l[Mm * Nn];
__device__ __align__(128) __nv_bfloat16 g_ATi_h[Nn * Mm];
__device__ __align__(128) __nv_bfloat16 g_ATi_l[Nn * Mm];
__device__ __align__(128) __nv_bfloat16 g_xu_h[(size_t)Bsz * Nn];
__device__ __align__(128) __nv_bfloat16 g_xu_l[(size_t)Bsz * Nn];
__device__ __align__(128) __nv_bfloat16 g_u_h[(size_t)Bsz * Nn];
__device__ __align__(128) __nv_bfloat16 g_u_l[(size_t)Bsz * Nn];
__device__ __align__(128) __nv_bfloat16 g_z_h[(size_t)Bsz * Nn];
__device__ __align__(128) __nv_bfloat16 g_z_l[(size_t)Bsz * Nn];
// Q images in 128-row tiles (A-image layout): [8 rb][16 ch][128x64, 16 KB]
__device__ __align__(128) __nv_bfloat16 g_Qhi[Mm * Mm];
__device__ __align__(128) __nv_bfloat16 g_Qlo[Mm * Mm];
__device__ __align__(128) __nv_bfloat16 g_lAhi[(size_t)Bsz * Mm];
__device__ __align__(128) __nv_bfloat16 g_lAlo[(size_t)Bsz * Mm];
__device__ __align__(128) __nv_bfloat16 g_lBhi[(size_t)Bsz * Mm];
__device__ __align__(128) __nv_bfloat16 g_lBlo[(size_t)Bsz * Mm];

// ---------------- helpers ----------------
__device__ __forceinline__ uint32_t s2u(const void* p) {
    uint32_t a;
    asm("{ .reg .u64 t; cvta.to.shared.u64 t, %1; cvt.u32.u64 %0, t; }"
        : "=r"(a) : "l"(p));
    return a;
}
__device__ __forceinline__ uint32_t swz(uint32_t off) {
    return off ^ ((off >> 3) & 0x70);
}
__device__ __forceinline__ void mbar_init(uint32_t a, uint32_t cnt) {
    asm volatile("mbarrier.init.shared.b64 [%0], %1;" :: "r"(a), "r"(cnt) : "memory");
}
__device__ __forceinline__ void mbar_arrive_tx(uint32_t a, uint32_t bytes) {
    asm volatile("mbarrier.arrive.expect_tx.shared.b64 _, [%0], %1;"
                 :: "r"(a), "r"(bytes) : "memory");
}
__device__ __forceinline__ void mbar_wait(uint32_t a, uint32_t phase) {
    uint32_t done = 0;
    while (!done) {
        asm volatile(
            "{ .reg .pred p; mbarrier.try_wait.parity.shared.b64 p, [%1], %2; "
            "selp.b32 %0, 1, 0, p; }"
            : "=r"(done) : "r"(a), "r"(phase) : "memory");
    }
}
__device__ __forceinline__ void bulk_g2s(uint32_t dst, const void* src,
                                         uint32_t bytes, uint32_t mbar) {
    asm volatile(
        "cp.async.bulk.shared::cluster.global.mbarrier::complete_tx::bytes "
        "[%0], [%1], %2, [%3];"
        :: "r"(dst), "l"(src), "r"(bytes), "r"(mbar) : "memory");
}
__device__ __forceinline__ uint64_t mkdesc(uint32_t addr) {
    return ((uint64_t)2 << 61) | ((uint64_t)1 << 46) | ((uint64_t)64 << 32)
         | ((uint64_t)1 << 16) | ((addr >> 4) & 0x3FFF);
}
#define GEMM_IDESC ((1u<<4) | (1u<<7) | (1u<<10) | ((TN/8)<<17) | ((128/16)<<24))
#define PGD2_IDESC ((1u<<4) | (1u<<7) | (1u<<10) | ((256/8)<<17) | ((256/16)<<24))

__device__ __forceinline__ float bfbits2f(uint16_t u) {
    __nv_bfloat16_raw r; r.x = u;
    return __bfloat162float(__nv_bfloat16(r));
}
__device__ __forceinline__ uint16_t f2bfbits(float f) {
    __nv_bfloat16 h = __float2bfloat16(f);
    __nv_bfloat16_raw r = (__nv_bfloat16_raw)h;
    return r.x;
}

#if HAS_TCGEN05
__device__ __forceinline__ void mma_f16_ss(uint32_t d, uint64_t a, uint64_t b,
                                           uint32_t idesc, uint32_t en) {
    asm volatile(
        "{\n\t.reg .pred p;\n\tsetp.ne.u32 p, %5, 0;\n\t"
        "tcgen05.mma.cta_group::1.kind::f16 [%0], %1, %2, %3, {%4,%4,%4,%4}, p;\n\t}"
        :: "r"(d), "l"(a), "l"(b), "r"(idesc), "r"(0u), "r"(en) : "memory");
}
__device__ __forceinline__ void mma_f16_ss_cg2(uint32_t d, uint64_t a, uint64_t b,
                                               uint32_t idesc, uint32_t en) {
    asm volatile(
        "{\n\t.reg .pred p;\n\tsetp.ne.u32 p, %5, 0;\n\t"
        "tcgen05.mma.cta_group::2.kind::f16 [%0], %1, %2, %3, "
        "{%4,%4,%4,%4,%4,%4,%4,%4}, p;\n\t}"
        :: "r"(d), "l"(a), "l"(b), "r"(idesc), "r"(0u), "r"(en) : "memory");
}
__device__ __forceinline__ void tc_commit(uint32_t mbar) {
    asm volatile(
        "tcgen05.commit.cta_group::1.mbarrier::arrive::one.shared::cluster.b64 [%0];"
        :: "r"(mbar) : "memory");
}
__device__ __forceinline__ void tc_commit_mc2(uint32_t mbar) {
    asm volatile(
        "tcgen05.commit.cta_group::2.mbarrier::arrive::one.shared::cluster"
        ".multicast::cluster.b64 [%0], %1;"
        :: "r"(mbar), "h"((uint16_t)3) : "memory");
}
__device__ __forceinline__ void mbar_arrive_peer0(uint32_t local_addr) {
    asm volatile(
        "{\n\t.reg .b32 ra;\n\t"
        "mapa.shared::cluster.u32 ra, %0, 0;\n\t"
        "mbarrier.arrive.shared::cluster.b64 _, [ra];\n\t}"
        :: "r"(local_addr) : "memory");
}
__device__ __forceinline__ uint32_t ctarank() {
    uint32_t r;
    asm("mov.u32 %0, %%cluster_ctarank;" : "=r"(r));
    return r;
}
#define CLUSTER_SYNC_() do { \
    asm volatile("barrier.cluster.arrive.aligned;" ::: "memory"); \
    asm volatile("barrier.cluster.wait.aligned;" ::: "memory"); } while (0)

#define TC_ALLOC(sres, n) \
    asm volatile("tcgen05.alloc.cta_group::1.sync.aligned.shared::cta.b32 [%0], %1;" \
                 :: "r"(sres), "r"((uint32_t)(n)) : "memory")
#define TC_RELINQ() \
    asm volatile("tcgen05.relinquish_alloc_permit.cta_group::1.sync.aligned;")
#define TC_DEALLOC(t, n) \
    asm volatile("tcgen05.dealloc.cta_group::1.sync.aligned.b32 %0, %1;" :: "r"(t), "r"((uint32_t)(n)))
#define TC_ALLOC2(sres, n) \
    asm volatile("tcgen05.alloc.cta_group::2.sync.aligned.shared::cta.b32 [%0], %1;" \
                 :: "r"(sres), "r"((uint32_t)(n)) : "memory")
#define TC_RELINQ2() \
    asm volatile("tcgen05.relinquish_alloc_permit.cta_group::2.sync.aligned;")
#define TC_DEALLOC2(t, n) \
    asm volatile("tcgen05.dealloc.cta_group::2.sync.aligned.b32 %0, %1;" :: "r"(t), "r"((uint32_t)(n)))
#define TC_FENCE_AFTER()  asm volatile("tcgen05.fence::after_thread_sync;" ::: "memory")
#define TC_WAIT_LD()      asm volatile("tcgen05.wait::ld.sync.aligned;" ::: "memory")
#define LDTM_X32(r, a) \
    asm volatile( \
        "tcgen05.ld.sync.aligned.32x32b.x32.b32 " \
        "{%0,%1,%2,%3,%4,%5,%6,%7,%8,%9,%10,%11,%12,%13,%14,%15," \
        "%16,%17,%18,%19,%20,%21,%22,%23,%24,%25,%26,%27,%28,%29,%30,%31}, [%32];" \
        : "=r"((r)[0]),"=r"((r)[1]),"=r"((r)[2]),"=r"((r)[3]), \
          "=r"((r)[4]),"=r"((r)[5]),"=r"((r)[6]),"=r"((r)[7]), \
          "=r"((r)[8]),"=r"((r)[9]),"=r"((r)[10]),"=r"((r)[11]), \
          "=r"((r)[12]),"=r"((r)[13]),"=r"((r)[14]),"=r"((r)[15]), \
          "=r"((r)[16]),"=r"((r)[17]),"=r"((r)[18]),"=r"((r)[19]), \
          "=r"((r)[20]),"=r"((r)[21]),"=r"((r)[22]),"=r"((r)[23]), \
          "=r"((r)[24]),"=r"((r)[25]),"=r"((r)[26]),"=r"((r)[27]), \
          "=r"((r)[28]),"=r"((r)[29]),"=r"((r)[30]),"=r"((r)[31]) \
        : "r"(a))
#endif  // HAS_TCGEN05

// ---------------------------------------------------------------------------
// cg2 PGD iteration: cluster(2), pair computes 256 rows x 256 cols.
//   Each CTA loads its 128 lam rows (A) and its 128 Q rows (B N-split).
//   rank0 issues cg2 MMAs; commits multicast to both CTAs.
// ---------------------------------------------------------------------------
__global__ void __launch_bounds__(256, 1) __cluster_dims__(2, 1, 1) pgd_cg2(
    const __nv_bfloat16* __restrict__ Ahi, const __nv_bfloat16* __restrict__ Alo,
    const __nv_bfloat16* __restrict__ Bhi, const __nv_bfloat16* __restrict__ Blo,
    const float* __restrict__ cc, const float* __restrict__ act,
    __nv_bfloat16* __restrict__ ohi, __nv_bfloat16* __restrict__ olo,
    int masked)
{
#if HAS_TCGEN05
    extern __shared__ char draw[];
    const uint32_t dsm = (s2u(draw) + 1023u) & ~1023u;

    __shared__ uint32_t s_tmem;
    __shared__ __align__(8) uint64_t s_bar[7]; // f0,f1,e0,e1,db,pf0,pf1

    const int tid  = threadIdx.x;
    const int wid  = tid >> 5;
    const int lane = tid & 31;
    const uint32_t rank = ctarank();

    const uint32_t f0  = s2u(&s_bar[0]);
    const uint32_t f1  = s2u(&s_bar[1]);
    const uint32_t e0  = s2u(&s_bar[2]);
    const uint32_t e1  = s2u(&s_bar[3]);
    const uint32_t db  = s2u(&s_bar[4]);
    const uint32_t pf0 = s2u(&s_bar[5]);
    const uint32_t pf1 = s2u(&s_bar[6]);

    if (wid == 0) TC_ALLOC2(s2u(&s_tmem), 256);
    if (tid == 0) {
        mbar_init(f0, 1); mbar_init(f1, 1);
        mbar_init(e0, 1); mbar_init(e1, 1);
        mbar_init(db, 1);
        mbar_init(pf0, 1); mbar_init(pf1, 1);
    }
    __syncthreads();
    uint32_t tmem;
    asm volatile("ld.shared.b32 %0, [%1];" : "=r"(tmem) : "r"(s2u(&s_tmem)));

    // barriers of rank0 must be initialized before rank1's cluster arrives
    CLUSTER_SYNC_();

    const int bmA = blockIdx.y * 2 + (int)rank;       // lam row-block (128 rows)
    const char* aH = (const char*)Ahi + (size_t)bmA * 16 * TILEA_B;
    const char* aL = (const char*)Alo + (size_t)bmA * 16 * TILEA_B;
    const char* bH = (const char*)Bhi + (size_t)blockIdx.x * 16 * TILEA_B;
    const char* bL = (const char*)Blo + (size_t)blockIdx.x * 16 * TILEA_B;

    if (tid == 0) {
        auto loadch = [&](int ch) {
            const int s = ch & 1;
            const uint32_t fb = s ? f1 : f0;
            const uint32_t st = dsm + (uint32_t)s * STG2_SZ;
            mbar_arrive_tx(fb, (uint32_t)STG2_SZ);
            bulk_g2s(st,         aH + (size_t)ch * TILEA_B, TILEA_B, fb);
            bulk_g2s(st + 16384, aL + (size_t)ch * TILEA_B, TILEA_B, fb);
            bulk_g2s(st + 32768, bH + (size_t)ch * TILEA_B, TILEA_B, fb);
            bulk_g2s(st + 49152, bL + (size_t)ch * TILEA_B, TILEA_B, fb);
        };
        loadch(0);
        loadch(1);

        uint32_t phf[2] = {0, 0}, phe[2] = {0, 0}, php[2] = {0, 0};
#pragma unroll 1
        for (int ch = 0; ch < 16; ch++) {
            const int s = ch & 1;
            mbar_wait(s ? f1 : f0, phf[s]); phf[s] ^= 1;

            if (rank == 1) {
                mbar_arrive_peer0(s ? pf1 : pf0);
            } else {
                mbar_wait(s ? pf1 : pf0, php[s]); php[s] ^= 1;
                const uint32_t st = dsm + (uint32_t)s * STG2_SZ;
                const uint64_t dah = mkdesc(st);
                const uint64_t dal = mkdesc(st + 16384);
                const uint64_t dbh = mkdesc(st + 32768);
                const uint64_t dbl = mkdesc(st + 49152);
#pragma unroll
                for (int ks = 0; ks < 4; ks++) {
                    mma_f16_ss_cg2(tmem, dah + ks * 2, dbh + ks * 2, PGD2_IDESC,
                                   (ch == 0 && ks == 0) ? 0u : 1u);
                    mma_f16_ss_cg2(tmem, dah + ks * 2, dbl + ks * 2, PGD2_IDESC, 1u);
                    mma_f16_ss_cg2(tmem, dal + ks * 2, dbh + ks * 2, PGD2_IDESC, 1u);
                }
                tc_commit_mc2(s ? e1 : e0);
            }

            mbar_wait(s ? e1 : e0, phe[s]); phe[s] ^= 1;
            if (ch + 2 < 16) loadch(ch + 2);
        }
        if (rank == 0) tc_commit_mc2(db);
    }

    mbar_wait(db, 0);
    TC_FENCE_AFTER();

    // ---------------- fused epilogue (each CTA: its 128 rows x 256 cols) ----------------
    const int sp   = wid & 3;
    const int half = wid >> 2;
    const int lr   = sp * 32 + lane;                  // local row 0..127
    const int r    = blockIdx.y * 256 + (int)rank * 128 + lr;
    const int n0   = (blockIdx.x >> 1) * 256;

#pragma unroll 1
    for (int cb = 0; cb < 128; cb += 32) {
        uint32_t dreg[32];
        LDTM_X32(dreg, tmem + half * 128 + cb);
        TC_WAIT_LD();

        const int coff = half * 128 + cb;
        const int gch  = (n0 + coff) >> 6;
        const int lc0  = coff & 63;
        const size_t tbA  = ((size_t)(bmA * 16 + gch)) * TILEA_B;
        const size_t blin = (size_t)r * Mm + n0 + coff;

#pragma unroll
        for (int j0 = 0; j0 < 32; j0 += 4) {
            const uint32_t boff = swz((uint32_t)(lr * 128 + (lc0 + j0) * 2));
            float4 cv = *(const float4*)&cc[blin + j0];
            uint64_t h4 = *(const uint64_t*)((const char*)Ahi + tbA + boff);
            uint64_t l4 = *(const uint64_t*)((const char*)Alo + tbA + boff);
            float4 av;
            if (masked) av = *(const float4*)&act[blin + j0];
            const float* cvp = (const float*)&cv;
            const float* avp = (const float*)&av;
            uint16_t oh[4], ol[4];
#pragma unroll
            for (int k = 0; k < 4; k++) {
                float lamold = bfbits2f((uint16_t)(h4 >> (16 * k)))
                             + bfbits2f((uint16_t)(l4 >> (16 * k)));
                float acc = __uint_as_float(dreg[j0 + k]);
                float v = fmaxf(lamold - STEPC * (acc - cvp[k]), 0.f);
                if (masked) v *= avp[k];
                uint16_t hb = f2bfbits(v);
                oh[k] = hb; ol[k] = f2bfbits(v - bfbits2f(hb));
            }
            *(uint64_t*)((char*)ohi + tbA + boff) =
                (uint64_t)oh[0] | ((uint64_t)oh[1] << 16)
                | ((uint64_t)oh[2] << 32) | ((uint64_t)oh[3] << 48);
            *(uint64_t*)((char*)olo + tbA + boff) =
                (uint64_t)ol[0] | ((uint64_t)ol[1] << 16)
                | ((uint64_t)ol[2] << 32) | ((uint64_t)ol[3] << 48);
        }
    }

    __syncthreads();
    if (wid == 0) { TC_RELINQ2(); TC_DEALLOC2(tmem, 256); }
    CLUSTER_SYNC_();
#endif  // HAS_TCGEN05
}

// epilogue variants (cg1 peripheral GEMMs)
enum { E_C = 0, E_ACT, E_MSK, E_Z, E_OUT, E_Q };

// ---------------------------------------------------------------------------
// Generic cg1 tcgen05 GEMM over pre-swizzled tile images, fused epilogues.
// ---------------------------------------------------------------------------
template <int EPI>
__global__ void __launch_bounds__(256, 1) tc_gemm(
    const __nv_bfloat16* __restrict__ Ahi, const __nv_bfloat16* __restrict__ Alo,
    const __nv_bfloat16* __restrict__ Bhi, const __nv_bfloat16* __restrict__ Blo,
    int nch,
    const float* __restrict__ v1, const float* __restrict__ v2,
    float* __restrict__ o32,
    __nv_bfloat16* __restrict__ ohi, __nv_bfloat16* __restrict__ olo,
    int Ncols)
{
#if HAS_TCGEN05
    extern __shared__ char draw[];
    const uint32_t dsm = (s2u(draw) + 1023u) & ~1023u;

    __shared__ uint32_t s_tmem;
    __shared__ __align__(8) uint64_t s_bar[5];

    const int tid  = threadIdx.x;
    const int wid  = tid >> 5;
    const int lane = tid & 31;
    const int bm0  = blockIdx.y * TM;
    const int bn0  = blockIdx.x * TN;

    const uint32_t f0 = s2u(&s_bar[0]);
    const uint32_t f1 = s2u(&s_bar[1]);
    const uint32_t e0 = s2u(&s_bar[2]);
    const uint32_t e1 = s2u(&s_bar[3]);
    const uint32_t db = s2u(&s_bar[4]);

    if (wid == 0) TC_ALLOC(s2u(&s_tmem), 256);
    if (tid == 0) {
        mbar_init(f0, 1); mbar_init(f1, 1);
        mbar_init(e0, 1); mbar_init(e1, 1);
        mbar_init(db, 1);
    }
    __syncthreads();
    uint32_t tmem;
    asm volatile("ld.shared.b32 %0, [%1];" : "=r"(tmem) : "r"(s2u(&s_tmem)));

    if (tid == 0) {
        const char* aH = (const char*)Ahi + (size_t)blockIdx.y * nch * TILEA_B;
        const char* aL = (const char*)Alo + (size_t)blockIdx.y * nch * TILEA_B;
        const char* bH = (const char*)Bhi + (size_t)blockIdx.x * nch * TILEB_B;
        const char* bL = (const char*)Blo + (size_t)blockIdx.x * nch * TILEB_B;

        auto loadch = [&](int ch) {
            const int s = ch & 1;
            const uint32_t fb = s ? f1 : f0;
            const uint32_t st = dsm + (uint32_t)s * STG_SZ;
            mbar_arrive_tx(fb, (uint32_t)STG_SZ);
            bulk_g2s(st,           aH + (size_t)ch * TILEA_B, TILEA_B, fb);
            bulk_g2s(st + OFF_ALO, aL + (size_t)ch * TILEA_B, TILEA_B, fb);
            bulk_g2s(st + OFF_BHI, bH + (size_t)ch * TILEB_B, TILEB_B, fb);
            bulk_g2s(st + OFF_BLO, bL + (size_t)ch * TILEB_B, TILEB_B, fb);
        };
        loadch(0);
        loadch(1);

        uint32_t phf[2] = {0, 0}, phe[2] = {0, 0};
#pragma unroll 1
        for (int ch = 0; ch < nch; ch++) {
            const int s = ch & 1;
            mbar_wait(s ? f1 : f0, phf[s]); phf[s] ^= 1;

            const uint32_t st = dsm + (uint32_t)s * STG_SZ;
            const uint64_t dah = mkdesc(st);
            const uint64_t dal = mkdesc(st + OFF_ALO);
            const uint64_t dbh = mkdesc(st + OFF_BHI);
            const uint64_t dbl = mkdesc(st + OFF_BLO);
#pragma unroll
            for (int ks = 0; ks < 4; ks++) {
                mma_f16_ss(tmem, dah + ks * 2, dbh + ks * 2, GEMM_IDESC,
                           (ch == 0 && ks == 0) ? 0u : 1u);
                mma_f16_ss(tmem, dah + ks * 2, dbl + ks * 2, GEMM_IDESC, 1u);
                mma_f16_ss(tmem, dal + ks * 2, dbh + ks * 2, GEMM_IDESC, 1u);
            }
            tc_commit(s ? e1 : e0);

            if (ch + 2 < nch) {
                mbar_wait(s ? e1 : e0, phe[s]); phe[s] ^= 1;
                loadch(ch + 2);
            }
        }
        tc_commit(db);
    }

    mbar_wait(db, 0);
    TC_FENCE_AFTER();

    const int sp   = wid & 3;
    const int half = wid >> 2;
    const int lr   = sp * 32 + lane;
    const int r    = bm0 + lr;
    const int nchO = Ncols >> 6;

#pragma unroll 1
    for (int cb = 0; cb < 128; cb += 32) {
        uint32_t dreg[32];
        LDTM_X32(dreg, tmem + half * 128 + cb);
        TC_WAIT_LD();

        const int coff = half * 128 + cb;
        const int gch  = (bn0 + coff) >> 6;
        const int lc0  = coff & 63;
        const size_t blin = (size_t)r * Ncols + bn0 + coff;
        const size_t tbA = ((size_t)(blockIdx.y * nchO + gch)) * TILEA_B;
        // E_Q: 128-row-tile layout (A-image style)
        const size_t tbQ = ((size_t)((r >> 7) * nchO + gch)) * TILEA_B;

#pragma unroll
        for (int j0 = 0; j0 < 32; j0 += 4) {
            const uint32_t boffA = swz((uint32_t)(lr * 128 + (lc0 + j0) * 2));
            float res[4];
#pragma unroll
            for (int k = 0; k < 4; k++) res[k] = __uint_as_float(dreg[j0 + k]);

            if (EPI == E_C) {
                float4 bv = *(const float4*)&v1[bn0 + coff + j0];
                const float* bp = (const float*)&bv;
                uint16_t oh[4], ol[4];
                float cvv[4];
#pragma unroll
                for (int k = 0; k < 4; k++) {
                    float cv = res[k] - bp[k];
                    cvv[k] = cv;
                    float v = fmaxf(STEPC * cv, 0.f);
                    uint16_t hb = f2bfbits(v);
                    oh[k] = hb; ol[k] = f2bfbits(v - bfbits2f(hb));
                }
                *(float4*)&o32[blin + j0] = make_float4(cvv[0], cvv[1], cvv[2], cvv[3]);
                *(uint64_t*)((char*)ohi + tbA + boffA) =
                    (uint64_t)oh[0] | ((uint64_t)oh[1] << 16)
                    | ((uint64_t)oh[2] << 32) | ((uint64_t)oh[3] << 48);
                *(uint64_t*)((char*)olo + tbA + boffA) =
                    (uint64_t)ol[0] | ((uint64_t)ol[1] << 16)
                    | ((uint64_t)ol[2] << 32) | ((uint64_t)ol[3] << 48);
            } else if (EPI == E_ACT) {
                float4 bv = *(const float4*)&v1[bn0 + coff + j0];
                const float* bp = (const float*)&bv;
                float o[4];
#pragma unroll
                for (int k = 0; k < 4; k++)
                    o[k] = (res[k] >= bp[k] - TOLV) ? 1.f : 0.f;
                *(float4*)&o32[blin + j0] = make_float4(o[0], o[1], o[2], o[3]);
            } else if (EPI == E_MSK) {
                float4 av = *(const float4*)&v1[blin + j0];
                const float* ap = (const float*)&av;
                uint16_t oh[4], ol[4];
                float mm[4];
#pragma unroll
                for (int k = 0; k < 4; k++) {
                    float m = res[k] * ap[k];
                    mm[k] = m;
                    float v = fmaxf(STEPC * m, 0.f) * ap[k];
                    uint16_t hb = f2bfbits(v);
                    oh[k] = hb; ol[k] = f2bfbits(v - bfbits2f(hb));
                }
                *(float4*)&o32[blin + j0] = make_float4(mm[0], mm[1], mm[2], mm[3]);
                *(uint64_t*)((char*)ohi + tbA + boffA) =
                    (uint64_t)oh[0] | ((uint64_t)oh[1] << 16)
                    | ((uint64_t)oh[2] << 32) | ((uint64_t)oh[3] << 48);
                *(uint64_t*)((char*)olo + tbA + boffA) =
                    (uint64_t)ol[0] | ((uint64_t)ol[1] << 16)
                    | ((uint64_t)ol[2] << 32) | ((uint64_t)ol[3] << 48);
            } else if (EPI == E_Z) {
                float4 xv = *(const float4*)&v1[blin + j0];
                float4 uv = *(const float4*)&v2[blin + j0];
                const float* xp = (const float*)&xv;
                const float* up = (const float*)&uv;
                uint16_t oh[4], ol[4];
#pragma unroll
                for (int k = 0; k < 4; k++) {
                    float zv = xp[k] + up[k] - res[k];
                    uint16_t hb = f2bfbits(zv);
                    oh[k] = hb; ol[k] = f2bfbits(zv - bfbits2f(hb));
                }
                *(uint64_t*)((char*)ohi + tbA + boffA) =
                    (uint64_t)oh[0] | ((uint64_t)oh[1] << 16)
                    | ((uint64_t)oh[2] << 32) | ((uint64_t)oh[3] << 48);
                *(uint64_t*)((char*)olo + tbA + boffA) =
                    (uint64_t)ol[0] | ((uint64_t)ol[1] << 16)
                    | ((uint64_t)ol[2] << 32) | ((uint64_t)ol[3] << 48);
            } else if (EPI == E_OUT) {
                float4 uv = *(const float4*)&v1[blin + j0];
                const float* up = (const float*)&uv;
                float o[4];
#pragma unroll
                for (int k = 0; k < 4; k++) o[k] = up[k] - res[k];
                *(float4*)&o32[blin + j0] = make_float4(o[0], o[1], o[2], o[3]);
            } else if (EPI == E_Q) {
                uint16_t oh[4], ol[4];
#pragma unroll
                for (int k = 0; k < 4; k++) {
                    uint16_t hb = f2bfbits(res[k]);
                    oh[k] = hb; ol[k] = f2bfbits(res[k] - bfbits2f(hb));
                }
                *(uint64_t*)((char*)ohi + tbQ + boffA) =
                    (uint64_t)oh[0] | ((uint64_t)oh[1] << 16)
                    | ((uint64_t)oh[2] << 32) | ((uint64_t)oh[3] << 48);
                *(uint64_t*)((char*)olo + tbQ + boffA) =
                    (uint64_t)ol[0] | ((uint64_t)ol[1] << 16)
                    | ((uint64_t)ol[2] << 32) | ((uint64_t)ol[3] << 48);
            }
        }
    }

    __syncthreads();
    if (wid == 0) { TC_RELINQ(); TC_DEALLOC(tmem, 256); }
#endif  // HAS_TCGEN05
}

// ---------------- prep kernels ----------------
__device__ __forceinline__ void img_store(__nv_bfloat16* hi, __nv_bfloat16* lo,
                                          size_t tb, uint32_t boff, float v)
{
    __nv_bfloat16 h = __float2bfloat16(v);
    *(__nv_bfloat16*)((char*)hi + tb + boff) = h;
    *(__nv_bfloat16*)((char*)lo + tb + boff) = __float2bfloat16(v - __bfloat162float(h));
}

__global__ void split_A_images(const float* __restrict__ A)
{
    int i = blockIdx.x * blockDim.x + threadIdx.x;
    if (i >= Mm * Nn) return;
    int r = i >> 9, k = i & 511;
    float v = A[i];
    int ch = k >> 6, lc = k & 63;
    {
        int bm = r >> 7, lrow = r & 127;
        size_t tb = ((size_t)(bm * 8 + ch)) * TILEA_B;
        img_store(g_AAi_h, g_AAi_l, tb, swz((uint32_t)(lrow * 128 + lc * 2)), v);
    }
    {
        int nb = r >> 8, brow = r & 255;
        size_t tb = ((size_t)(nb * 8 + ch)) * TILEB_B;
        img_store(g_ABi_h, g_ABi_l, tb, swz((uint32_t)(brow * 128 + lc * 2)), v);
    }
}

__global__ void split_AT_image(const float* __restrict__ A)
{
    int i = blockIdx.x * blockDim.x + threadIdx.x;
    if (i >= Nn * Mm) return;
    int n = i >> 10, k = i & 1023;
    float v = A[(size_t)k * Nn + n];
    int nb = n >> 8, brow = n & 255, ch = k >> 6, lc = k & 63;
    size_t tb = ((size_t)(nb * 16 + ch)) * TILEB_B;
    img_store(g_ATi_h, g_ATi_l, tb, swz((uint32_t)(brow * 128 + lc * 2)), v);
}

__global__ void split_xu_u(const float* __restrict__ x, const float* __restrict__ u)
{
    int i = blockIdx.x * blockDim.x + threadIdx.x;
    if (i >= Bsz * Nn) return;
    int r = i >> 9, k = i & 511;
    int bm = r >> 7, lrow = r & 127, ch = k >> 6, lc = k & 63;
    size_t tb = ((size_t)(bm * 8 + ch)) * TILEA_B;
    uint32_t boff = swz((uint32_t)(lrow * 128 + lc * 2));
    float uv = u[i];
    img_store(g_xu_h, g_xu_l, tb, boff, x[i] + uv);
    img_store(g_u_h,  g_u_l,  tb, boff, uv);
}

// ---------------------------------------------------------------------------
extern "C" void kernel_launch(void* const* d_in, const int* in_sizes, int n_in,
                              void* d_out, int out_size)
{
    const float* x = (const float*)d_in[0];
    const float* u = (const float*)d_in[1];
    const float* A = (const float*)d_in[2];
    const float* b = (const float*)d_in[3];
    float* out = (float*)d_out;

    float *c, *msk, *act;
    __nv_bfloat16 *AAh, *AAl, *ABh, *ABl, *ATh, *ATl, *XUh, *XUl, *Uh, *Ul,
                  *Zh, *Zl, *Qh, *Ql, *lAh, *lAl, *lBh, *lBl;
    cudaGetSymbolAddress((void**)&c,   g_c);
    cudaGetSymbolAddress((void**)&msk, g_msk);
    cudaGetSymbolAddress((void**)&act, g_act);
    cudaGetSymbolAddress((void**)&AAh, g_AAi_h); cudaGetSymbolAddress((void**)&AAl, g_AAi_l);
    cudaGetSymbolAddress((void**)&ABh, g_ABi_h); cudaGetSymbolAddress((void**)&ABl, g_ABi_l);
    cudaGetSymbolAddress((void**)&ATh, g_ATi_h); cudaGetSymbolAddress((void**)&ATl, g_ATi_l);
    cudaGetSymbolAddress((void**)&XUh, g_xu_h);  cudaGetSymbolAddress((void**)&XUl, g_xu_l);
    cudaGetSymbolAddress((void**)&Uh,  g_u_h);   cudaGetSymbolAddress((void**)&Ul,  g_u_l);
    cudaGetSymbolAddress((void**)&Zh,  g_z_h);   cudaGetSymbolAddress((void**)&Zl,  g_z_l);
    cudaGetSymbolAddress((void**)&Qh,  g_Qhi);   cudaGetSymbolAddress((void**)&Ql,  g_Qlo);
    cudaGetSymbolAddress((void**)&lAh, g_lAhi);  cudaGetSymbolAddress((void**)&lAl, g_lAlo);
    cudaGetSymbolAddress((void**)&lBh, g_lBhi);  cudaGetSymbolAddress((void**)&lBl, g_lBlo);

    cudaFuncSetAttribute(tc_gemm<E_C>,   cudaFuncAttributeMaxDynamicSharedMemorySize, DSMEM);
    cudaFuncSetAttribute(tc_gemm<E_ACT>, cudaFuncAttributeMaxDynamicSharedMemorySize, DSMEM);
    cudaFuncSetAttribute(tc_gemm<E_MSK>, cudaFuncAttributeMaxDynamicSharedMemorySize, DSMEM);
    cudaFuncSetAttribute(tc_gemm<E_Z>,   cudaFuncAttributeMaxDynamicSharedMemorySize, DSMEM);
    cudaFuncSetAttribute(tc_gemm<E_OUT>, cudaFuncAttributeMaxDynamicSharedMemorySize, DSMEM);
    cudaFuncSetAttribute(tc_gemm<E_Q>,   cudaFuncAttributeMaxDynamicSharedMemorySize, DSMEM);
    cudaFuncSetAttribute(pgd_cg2,        cudaFuncAttributeMaxDynamicSharedMemorySize, DSMEM2);

    const dim3 blk(256);
    const int EW = 256;

    // prep
    split_A_images<<<(Mm * Nn + EW - 1) / EW, EW>>>(A);
    split_AT_image<<<(Nn * Mm + EW - 1) / EW, EW>>>(A);
    split_xu_u<<<(int)(((size_t)Bsz * Nn + EW - 1) / EW), EW>>>(x, u);

    // Q = A @ A^T -> Q images (128-row tiles)
    tc_gemm<E_Q><<<dim3(4, 8), blk, DSMEM>>>(AAh, AAl, ABh, ABl, 8,
                                             nullptr, nullptr, nullptr, Qh, Ql, 1024);

    // c = xu @ A^T - b (+ lam init)
    tc_gemm<E_C><<<dim3(4, 32), blk, DSMEM>>>(XUh, XUl, ABh, ABl, 8,
                                              b, nullptr, c, lAh, lAl, 1024);

    // PGD iters 2..50, cg2 (grid 8 x 16 = 128 CTAs, 64 pairs)
    __nv_bfloat16 *curh = lAh, *curl = lAl, *nxth = lBh, *nxtl = lBl;
    for (int it = 1; it < 50; it++) {
        pgd_cg2<<<dim3(8, 16), blk, DSMEM2>>>(curh, curl, Qh, Ql,
                                              c, nullptr, nxth, nxtl, 0);
        __nv_bfloat16* t;
        t = curh; curh = nxth; nxth = t;
        t = curl; curl = nxtl; nxtl = t;
    }

    // z = x + u - lam @ A
    tc_gemm<E_Z><<<dim3(2, 32), blk, DSMEM>>>(curh, curl, ATh, ATl, 16,
                                              x, u, nullptr, Zh, Zl, 512);
    // active
    tc_gemm<E_ACT><<<dim3(4, 32), blk, DSMEM>>>(Zh, Zl, ABh, ABl, 8,
                                                b, nullptr, act, nullptr, nullptr, 1024);
    // masked (+ masked lam init)
    tc_gemm<E_MSK><<<dim3(4, 32), blk, DSMEM>>>(Uh, Ul, ABh, ABl, 8,
                                                act, nullptr, msk, lAh, lAl, 1024);

    // masked PGD iters 2..10, cg2
    curh = lAh; curl = lAl; nxth = lBh; nxtl = lBl;
    for (int it = 1; it < 10; it++) {
        pgd_cg2<<<dim3(8, 16), blk, DSMEM2>>>(curh, curl, Qh, Ql,
                                              msk, act, nxth, nxtl, 1);
        __nv_bfloat16* t;
        t = curh; curh = nxth; nxth = t;
        t = curl; curl = nxtl; nxtl = t;
    }

    // out = u - lam @ A
    tc_gemm<E_OUT><<<dim3(2, 32), blk, DSMEM>>>(curh, curl, ATh, ATl, 16,
                                                u, nullptr, out, nullptr, nullptr, 512);
}